// round 12
// baseline (speedup 1.0000x reference)
#include <cuda_runtime.h>
#include <math.h>

#define BB 2048
#define CC 3
#define TT 300
#define JJ 25
#define TJ (TT * JJ)            // 7500 elements per (b,c) slice
#define NSLICE (BB * CC)        // 6144 slices
#define SPB 4                   // slices per block; each slice = 2 warps
#define WPB (SPB * 2)           // 8 warps per block
#define NBLK (NSLICE / SPB)     // 1536 blocks -> 12288 warps -> 64 warps/SM
#define NTHREADS (WPB * 32)
#define NF4 (TJ / 4)            // 1875 float4 per slice
#define KMAX (NF4 / JJ)         // 75 groups of 25 float4 (= 4 frames each)
#define KSPLIT 38               // half 0: k in [0,38)   half 1: k in [38,75)

// Global accumulators (allocation-free scratch). Zero-initialized at load;
// last finishing block resets them -> deterministic across graph replays.
__device__ double g_rec = 0.0;
__device__ double g_smooth = 0.0;
__device__ unsigned int g_count = 0u;

// Element (lane,kk) of any group k: j = (4*lane+kk) % 25 -- k-invariant.
// Interior contribution to (sx - st): d - d*(x+t), d = x-t.
// FIRST (k==0, elements with 4l+kk<25 are t==0): those get only +d.
// LAST  (k==74, elements with 4l+kk>=75 are t==299): those get only -d*(x+t).
template <bool FIRST, bool LAST>
__device__ __forceinline__ void process4(float4 xv, float4 tv, int fourl,
                                         float acc[4], float& rec) {
    const float xa[4] = {xv.x, xv.y, xv.z, xv.w};
    const float ta[4] = {tv.x, tv.y, tv.z, tv.w};
    #pragma unroll
    for (int kk = 0; kk < 4; kk++) {
        const float d  = xa[kk] - ta[kk];
        rec = fmaf(d, d, rec);
        const float xt = xa[kk] + ta[kk];
        float c;
        if (FIRST) {
            c = d;
            if (fourl + kk >= 25) c = fmaf(-d, xt, c);
        } else if (LAST) {
            c = (fourl + kk < 75) ? d : 0.0f;
            c = fmaf(-d, xt, c);
        } else {
            c = fmaf(-d, xt, d);
        }
        acc[kk] += c;
    }
}

__global__ void __launch_bounds__(NTHREADS)
loss_kernel(const float* __restrict__ x, const float* __restrict__ tg,
            float* __restrict__ out) {
    const int warp = threadIdx.x >> 5;
    const int lane = threadIdx.x & 31;
    const int sidx = warp >> 1;                    // slice within block (0..3)
    const int half = warp & 1;                     // k-range half
    const int slice = blockIdx.x * SPB + sidx;     // < 6144

    const float4* __restrict__ x4 = (const float4*)(x  + (size_t)slice * TJ);
    const float4* __restrict__ t4 = (const float4*)(tg + (size_t)slice * TJ);

    const bool active = (lane < JJ);
    const int fourl = lane * 4;

    __shared__ float sj[SPB][JJ];      // per-slice per-joint combined sums
    __shared__ double s_rec[WPB];
    __shared__ double s_sm[SPB];
    {
        float* flat = &sj[0][0];
        if (threadIdx.x < SPB * JJ) flat[threadIdx.x] = 0.0f;
    }
    __syncthreads();

    float acc[4] = {0.0f, 0.0f, 0.0f, 0.0f};
    float rec = 0.0f;
    const float4 z4 = {0.0f, 0.0f, 0.0f, 0.0f};

    if (half == 0) {
        // k = 0 (contains all t==0 elements)
        {
            float4 xv = active ? __ldg(x4 + lane) : z4;
            float4 tv = active ? __ldg(t4 + lane) : z4;
            process4<true, false>(xv, tv, fourl, acc, rec);
        }
        #pragma unroll 2
        for (int k = 1; k < KSPLIT; k++) {
            float4 xv = active ? __ldg(x4 + k * JJ + lane) : z4;
            float4 tv = active ? __ldg(t4 + k * JJ + lane) : z4;
            process4<false, false>(xv, tv, fourl, acc, rec);
        }
    } else {
        #pragma unroll 2
        for (int k = KSPLIT; k < KMAX - 1; k++) {
            float4 xv = active ? __ldg(x4 + k * JJ + lane) : z4;
            float4 tv = active ? __ldg(t4 + k * JJ + lane) : z4;
            process4<false, false>(xv, tv, fourl, acc, rec);
        }
        // k = 74 (contains all t==299 elements)
        {
            float4 xv = active ? __ldg(x4 + (KMAX - 1) * JJ + lane) : z4;
            float4 tv = active ? __ldg(t4 + (KMAX - 1) * JJ + lane) : z4;
            process4<false, true>(xv, tv, fourl, acc, rec);
        }
    }

    // rec: full-warp shuffle reduce.
    #pragma unroll
    for (int o = 16; o > 0; o >>= 1)
        rec += __shfl_xor_sync(0xffffffffu, rec, o);
    if (lane == 0) s_rec[warp] = (double)rec;

    // Fold 100 (lane,kk) accumulators per half into the slice's joint sums.
    if (active) {
        #pragma unroll
        for (int kk = 0; kk < 4; kk++) {
            const int v = fourl + kk;
            const int j = (v >= 75) ? v - 75 : (v >= 50) ? v - 50
                        : (v >= 25) ? v - 25 : v;
            atomicAdd(&sj[sidx][j], acc[kk]);
        }
    }
    __syncthreads();

    if (half == 0) {
        float av = (lane < JJ - 1) ? fabsf(sj[sidx][lane]) : 0.0f;
        #pragma unroll
        for (int o = 16; o > 0; o >>= 1)
            av += __shfl_xor_sync(0xffffffffu, av, o);
        if (lane == 0) s_sm[sidx] = sqrt((double)av) / (double)TJ;
    }
    __syncthreads();

    if (threadIdx.x == 0) {
        double rtot = 0.0, stot = 0.0;
        #pragma unroll
        for (int w = 0; w < WPB; w++) rtot += s_rec[w];
        #pragma unroll
        for (int s = 0; s < SPB; s++) stot += s_sm[s];
        atomicAdd(&g_rec, rtot);
        atomicAdd(&g_smooth, stot);
        __threadfence();
        const unsigned int ticket = atomicAdd(&g_count, 1u);
        if (ticket == NBLK - 1) {
            const double rec_sum = atomicAdd(&g_rec, 0.0);
            const double sm_sum  = atomicAdd(&g_smooth, 0.0);
            const double rec_mean    = rec_sum / ((double)BB * CC * TT * JJ);
            const double smooth_mean = sm_sum  / ((double)BB * CC);
            out[0] = (float)(2.0 * rec_mean + 3.0 * smooth_mean);
            g_rec = 0.0;
            g_smooth = 0.0;
            __threadfence();
            g_count = 0u;
        }
    }
}

extern "C" void kernel_launch(void* const* d_in, const int* in_sizes, int n_in,
                              void* d_out, int out_size) {
    const float* x  = (const float*)d_in[0];
    const float* tg = (const float*)d_in[1];
    float* out = (float*)d_out;

    loss_kernel<<<NBLK, NTHREADS>>>(x, tg, out);
}

// round 13
// speedup vs baseline: 1.0858x; 1.0858x over previous
#include <cuda_runtime.h>
#include <math.h>
#include <stdint.h>

#define BB 2048
#define CC 3
#define TT 300
#define JJ 25
#define TJ (TT * JJ)            // 7500 elements per (b,c) slice (30000 B)
#define NSLICE (BB * CC)        // 6144 slices
#define WPB 8                   // warps per block (1 warp = 1 slice)
#define NBLK (NSLICE / WPB)     // 768 blocks
#define NTHREADS (WPB * 32)
#define KMAX 75                 // 75 groups of 25 float4 (400 B each)
#define CHUNK 5                 // groups per pipeline chunk
#define NCHUNK (KMAX / CHUNK)   // 15 chunks per slice
#define STAGES 3
#define CHUNK_BYTES (CHUNK * JJ * 16)          // 2000 B per tensor per chunk
#define SLOT_BYTES (2 * CHUNK_BYTES)           // x + t per stage
#define WARP_SMEM (STAGES * SLOT_BYTES)        // 12000 B per warp
#define DYN_SMEM (WPB * WARP_SMEM)             // 96000 B per block

// Global accumulators (allocation-free scratch). Zero-initialized at load;
// last finishing block resets them -> deterministic across graph replays.
__device__ double g_rec = 0.0;
__device__ double g_smooth = 0.0;
__device__ unsigned int g_count = 0u;

// ---- PTX helpers -----------------------------------------------------------
__device__ __forceinline__ uint32_t smem_u32(const void* p) {
    return (uint32_t)__cvta_generic_to_shared(p);
}
__device__ __forceinline__ void mbar_init(uint32_t mbar, uint32_t cnt) {
    asm volatile("mbarrier.init.shared.b64 [%0], %1;"
                 :: "r"(mbar), "r"(cnt) : "memory");
}
__device__ __forceinline__ void mbar_expect_tx(uint32_t mbar, uint32_t bytes) {
    asm volatile("mbarrier.arrive.expect_tx.shared.b64 _, [%0], %1;"
                 :: "r"(mbar), "r"(bytes) : "memory");
}
__device__ __forceinline__ void bulk_g2s(uint32_t dst, const void* src,
                                         uint32_t bytes, uint32_t mbar) {
    asm volatile(
        "cp.async.bulk.shared::cluster.global.mbarrier::complete_tx::bytes "
        "[%0], [%1], %2, [%3];"
        :: "r"(dst), "l"(src), "r"(bytes), "r"(mbar) : "memory");
}
__device__ __forceinline__ void mbar_wait(uint32_t mbar, uint32_t phase) {
    asm volatile(
        "{\n\t.reg .pred P;\n\t"
        "WAIT_%=:\n\t"
        "mbarrier.try_wait.parity.acquire.cta.shared::cta.b64 P, [%0], %1, 0x989680;\n\t"
        "@P bra.uni DONE_%=;\n\t"
        "bra.uni WAIT_%=;\n\t"
        "DONE_%=:\n\t}"
        :: "r"(mbar), "r"(phase) : "memory");
}
__device__ __forceinline__ void fence_proxy_async_cta() {
    asm volatile("fence.proxy.async.shared::cta;" ::: "memory");
}

// Element (lane,kk) of any group k: j = (4*lane+kk) % 25 -- k-invariant.
// Interior contribution to (sx - st): d - d*(x+t), d = x-t.
// FIRST (k==0, 4l+kk<25 are t==0): only +d.
// LAST  (k==74, 4l+kk>=75 are t==299): only -d*(x+t).
template <bool FIRST, bool LAST>
__device__ __forceinline__ void process4(float4 xv, float4 tv, int fourl,
                                         float acc[4], float& rec) {
    const float xa[4] = {xv.x, xv.y, xv.z, xv.w};
    const float ta[4] = {tv.x, tv.y, tv.z, tv.w};
    #pragma unroll
    for (int kk = 0; kk < 4; kk++) {
        const float d  = xa[kk] - ta[kk];
        rec = fmaf(d, d, rec);
        const float xt = xa[kk] + ta[kk];
        float c;
        if (FIRST) {
            c = d;
            if (fourl + kk >= 25) c = fmaf(-d, xt, c);
        } else if (LAST) {
            c = (fourl + kk < 75) ? d : 0.0f;
            c = fmaf(-d, xt, c);
        } else {
            c = fmaf(-d, xt, d);
        }
        acc[kk] += c;
    }
}

extern __shared__ char dynsmem[];

__global__ void __launch_bounds__(NTHREADS)
loss_kernel(const float* __restrict__ x, const float* __restrict__ tg,
            float* __restrict__ out) {
    const int warp = threadIdx.x >> 5;
    const int lane = threadIdx.x & 31;
    const int slice = blockIdx.x * WPB + warp;          // < 6144

    const char* __restrict__ xsrc = (const char*)(x  + (size_t)slice * TJ);
    const char* __restrict__ tsrc = (const char*)(tg + (size_t)slice * TJ);

    char* wbase = dynsmem + warp * WARP_SMEM;

    __shared__ __align__(8) uint64_t mbar_store[WPB][STAGES];
    uint32_t mb[STAGES];
    #pragma unroll
    for (int s = 0; s < STAGES; s++) mb[s] = smem_u32(&mbar_store[warp][s]);

    if (lane == 0) {
        #pragma unroll
        for (int s = 0; s < STAGES; s++) mbar_init(mb[s], 1);
    }
    fence_proxy_async_cta();
    __syncwarp();

    // Prologue: fill all stages (chunks 0..STAGES-1).
    if (lane == 0) {
        #pragma unroll
        for (int s = 0; s < STAGES; s++) {
            mbar_expect_tx(mb[s], SLOT_BYTES);
            uint32_t dst = smem_u32(wbase + s * SLOT_BYTES);
            bulk_g2s(dst, xsrc + s * CHUNK_BYTES, CHUNK_BYTES, mb[s]);
            bulk_g2s(dst + CHUNK_BYTES, tsrc + s * CHUNK_BYTES, CHUNK_BYTES, mb[s]);
        }
    }

    const bool active = (lane < JJ);
    const int fourl = lane * 4;
    float acc[4] = {0.0f, 0.0f, 0.0f, 0.0f};
    float rec = 0.0f;
    const float4 z4 = {0.0f, 0.0f, 0.0f, 0.0f};

    for (int c = 0; c < NCHUNK; c++) {
        const int slot = c % STAGES;
        const uint32_t phase = (uint32_t)((c / STAGES) & 1);
        mbar_wait(mb[slot], phase);

        const float4* xb = (const float4*)(wbase + slot * SLOT_BYTES);
        const float4* tb = (const float4*)(wbase + slot * SLOT_BYTES + CHUNK_BYTES);

        #pragma unroll
        for (int g = 0; g < CHUNK; g++) {
            float4 xv = z4, tv = z4;
            if (active) { xv = xb[g * JJ + lane]; tv = tb[g * JJ + lane]; }
            const int k = c * CHUNK + g;
            if (c == 0 && g == 0)                     // k == 0
                process4<true, false>(xv, tv, fourl, acc, rec);
            else if (c == NCHUNK - 1 && g == CHUNK - 1)  // k == 74
                process4<false, true>(xv, tv, fourl, acc, rec);
            else
                process4<false, false>(xv, tv, fourl, acc, rec);
            (void)k;
        }

        __syncwarp();   // all lanes done reading this slot
        const int cn = c + STAGES;
        if (lane == 0 && cn < NCHUNK) {
            mbar_expect_tx(mb[slot], SLOT_BYTES);
            uint32_t dst = smem_u32(wbase + slot * SLOT_BYTES);
            bulk_g2s(dst, xsrc + cn * CHUNK_BYTES, CHUNK_BYTES, mb[slot]);
            bulk_g2s(dst + CHUNK_BYTES, tsrc + cn * CHUNK_BYTES, CHUNK_BYTES, mb[slot]);
        }
    }

    // rec: full-warp shuffle reduce.
    #pragma unroll
    for (int o = 16; o > 0; o >>= 1)
        rec += __shfl_xor_sync(0xffffffffu, rec, o);

    // Smooth: fold 100 (lane,kk) accumulators into per-joint sums via smem.
    __shared__ float sj[WPB][JJ];
    if (active) sj[warp][lane] = 0.0f;
    __syncwarp();
    if (active) {
        #pragma unroll
        for (int kk = 0; kk < 4; kk++) {
            const int v = fourl + kk;
            const int j = (v >= 75) ? v - 75 : (v >= 50) ? v - 50
                        : (v >= 25) ? v - 25 : v;
            atomicAdd(&sj[warp][j], acc[kk]);
        }
    }
    __syncwarp();

    float av = (lane < JJ - 1) ? fabsf(sj[warp][lane]) : 0.0f;
    #pragma unroll
    for (int o = 16; o > 0; o >>= 1)
        av += __shfl_xor_sync(0xffffffffu, av, o);

    __shared__ double s_rec[WPB];
    __shared__ double s_sm[WPB];
    if (lane == 0) {
        s_rec[warp] = (double)rec;
        s_sm[warp]  = sqrt((double)av) / (double)TJ;
    }
    __syncthreads();

    if (threadIdx.x == 0) {
        double rtot = 0.0, stot = 0.0;
        #pragma unroll
        for (int w = 0; w < WPB; w++) { rtot += s_rec[w]; stot += s_sm[w]; }
        atomicAdd(&g_rec, rtot);
        atomicAdd(&g_smooth, stot);
        __threadfence();
        const unsigned int ticket = atomicAdd(&g_count, 1u);
        if (ticket == NBLK - 1) {
            const double rec_sum = atomicAdd(&g_rec, 0.0);
            const double sm_sum  = atomicAdd(&g_smooth, 0.0);
            const double rec_mean    = rec_sum / ((double)BB * CC * TT * JJ);
            const double smooth_mean = sm_sum  / ((double)BB * CC);
            out[0] = (float)(2.0 * rec_mean + 3.0 * smooth_mean);
            g_rec = 0.0;
            g_smooth = 0.0;
            __threadfence();
            g_count = 0u;
        }
    }
}

extern "C" void kernel_launch(void* const* d_in, const int* in_sizes, int n_in,
                              void* d_out, int out_size) {
    const float* x  = (const float*)d_in[0];
    const float* tg = (const float*)d_in[1];
    float* out = (float*)d_out;

    cudaFuncSetAttribute(loss_kernel,
                         cudaFuncAttributeMaxDynamicSharedMemorySize, DYN_SMEM);
    loss_kernel<<<NBLK, NTHREADS, DYN_SMEM>>>(x, tg, out);
}